// round 6
// baseline (speedup 1.0000x reference)
#include <cuda_runtime.h>
#include <cuda_bf16.h>
#include <math.h>
#include <stdint.h>

#define BATCH 8
#define SEQ   2048
#define DIM   512
#define MTOT  (BATCH*SEQ)        // 16384

// ===========================================================================
// Scratch memory (single __device__ array; no allocation anywhere)
// ===========================================================================
#define SZ_X ((size_t)MTOT * DIM)                     // 8,388,608 elems
static const size_t O_XHI   = 0;                                // bf16 SZ_X
static const size_t O_XLO   = O_XHI   + SZ_X * 2;
static const size_t O_WHI   = O_XLO   + SZ_X * 2;               // bf16 3*DIM*DIM
static const size_t O_WLO   = O_WHI   + (size_t)3 * DIM * DIM * 2;
static const size_t O_QKVHI = O_WLO   + (size_t)3 * DIM * DIM * 2;  // bf16 3*SZ_X
static const size_t O_QKVLO = O_QKVHI + (size_t)3 * SZ_X * 2;
static const size_t O_VTHI  = O_QKVLO + (size_t)3 * SZ_X * 2;   // bf16 SZ_X (V^T)
static const size_t O_VTLO  = O_VTHI  + SZ_X * 2;
static const size_t O_S     = O_VTLO  + SZ_X * 2;               // fp32 B*S*S
static const size_t O_SHI   = O_S     + (size_t)BATCH * SEQ * SEQ * 4;
static const size_t O_SLO   = O_SHI   + (size_t)BATCH * SEQ * SEQ * 2;
static const size_t SCRATCH_TOTAL = O_SLO + (size_t)BATCH * SEQ * SEQ * 2;

__device__ __align__(1024) unsigned char g_scratch[SCRATCH_TOTAL];

// ===========================================================================
// PTX helpers (arch-agnostic: cp.async / ldmatrix / mma.sync only)
// ===========================================================================
__device__ __forceinline__ uint32_t smem_u32(const void* p) {
    uint32_t a;
    asm("{ .reg .u64 t; cvta.to.shared.u64 t, %1; cvt.u32.u64 %0, t; }"
        : "=r"(a) : "l"(p));
    return a;
}

#define SWZ128(x) ((x) ^ (((x) >> 3) & 0x70))

__device__ __forceinline__ void cp16(uint32_t dst, const void* src) {
    asm volatile("cp.async.cg.shared.global [%0], [%1], 16;\n"
                 :: "r"(dst), "l"(src));
}
__device__ __forceinline__ void cp_commit() {
    asm volatile("cp.async.commit_group;\n" ::: "memory");
}
template <int N> __device__ __forceinline__ void cp_wait() {
    asm volatile("cp.async.wait_group %0;\n" :: "n"(N) : "memory");
}

__device__ __forceinline__ void ldm_x4(uint32_t* r, uint32_t addr) {
    asm volatile("ldmatrix.sync.aligned.m8n8.x4.shared.b16 {%0,%1,%2,%3}, [%4];"
                 : "=r"(r[0]), "=r"(r[1]), "=r"(r[2]), "=r"(r[3]) : "r"(addr));
}

__device__ __forceinline__ void mma_bf16(float* c, const uint32_t* a,
                                         uint32_t b0, uint32_t b1) {
    asm volatile("mma.sync.aligned.m16n8k16.row.col.f32.bf16.bf16.f32 "
                 "{%0,%1,%2,%3}, {%4,%5,%6,%7}, {%8,%9}, {%0,%1,%2,%3};"
                 : "+f"(c[0]), "+f"(c[1]), "+f"(c[2]), "+f"(c[3])
                 : "r"(a[0]), "r"(a[1]), "r"(a[2]), "r"(a[3]), "r"(b0), "r"(b1));
}

// ===========================================================================
// HMMA GEMM:  C[M,N] = alpha * (Ahi@Bhi^T + Alo@Bhi^T + Ahi@Blo^T)   (bf16 NT)
// CTA tile 128(M) x 256(N), BK=64, 256 threads (8 warps, 64x64 warp tiles),
// double-buffered cp.async (2 x 96 KB stages).
// Epilogue: fp32*alpha if Chi==null, else bf16 hi/lo split.
// ===========================================================================
#define ST_BYTES 98304u          // Ah 16K | Al 16K | Bh 32K | Bl 32K
#define SMEM_GEMM (2 * 98304 + 1024)

__global__ __launch_bounds__(256, 1)
void hgemm3(const __nv_bfloat16* __restrict__ Ahi,
            const __nv_bfloat16* __restrict__ Alo,
            const __nv_bfloat16* __restrict__ Bhi,
            const __nv_bfloat16* __restrict__ Blo,
            float* __restrict__ C,
            __nv_bfloat16* __restrict__ Chi,
            __nv_bfloat16* __restrict__ Clo,
            int ldA, int ldB, int ldC, int kTiles,
            size_t sA, size_t sB, size_t sC, float alpha)
{
    extern __shared__ char smem_raw[];
    const uint32_t sbase = (smem_u32(smem_raw) + 1023u) & ~1023u;

    const int tid  = threadIdx.x;
    const int wid  = tid >> 5;
    const int lane = tid & 31;
    const int wm   = wid & 1;      // 2 M-warps -> 64 rows each
    const int wn   = wid >> 1;     // 4 N-warps -> 64 cols each

    const int row0 = blockIdx.y * 128;
    const int col0 = blockIdx.x * 256;

    Ahi += (size_t)blockIdx.z * sA;  Alo += (size_t)blockIdx.z * sA;
    Bhi += (size_t)blockIdx.z * sB;  Blo += (size_t)blockIdx.z * sB;

    float acc[4][8][4];
    #pragma unroll
    for (int mt = 0; mt < 4; mt++)
        #pragma unroll
        for (int j = 0; j < 8; j++)
            #pragma unroll
            for (int q = 0; q < 4; q++) acc[mt][j][q] = 0.f;

    // stage: [A_hi 16K][A_lo 16K][B_hi 32K][B_lo 32K]
    auto load_stage = [&](int t) {
        const int kk = t * 64;
        const uint32_t st = sbase + (uint32_t)(t & 1) * ST_BYTES;
        #pragma unroll
        for (int q = 0; q < 4; q++) {                 // A: 128 rows x 8 chunks
            int idx = tid + q * 256;
            int rr = idx >> 3, cc = idx & 7;
            uint32_t d = SWZ128((uint32_t)(rr * 128 + cc * 16));
            size_t oa = (size_t)(row0 + rr) * ldA + kk + cc * 8;
            cp16(st +          d, Ahi + oa);
            cp16(st + 16384u + d, Alo + oa);
        }
        #pragma unroll
        for (int q = 0; q < 8; q++) {                 // B: 256 rows x 8 chunks
            int idx = tid + q * 256;
            int rr = idx >> 3, cc = idx & 7;
            uint32_t d = SWZ128((uint32_t)(rr * 128 + cc * 16));
            size_t ob = (size_t)(col0 + rr) * ldB + kk + cc * 8;
            cp16(st + 32768u + d, Bhi + ob);
            cp16(st + 65536u + d, Blo + ob);
        }
        cp_commit();
    };

    load_stage(0);

    const uint32_t lrow = (uint32_t)(lane & 15);
    const uint32_t lcol = (uint32_t)((lane >> 4) * 16);

    for (int t = 0; t < kTiles; t++) {
        if (t + 1 < kTiles) {
            load_stage(t + 1);
            cp_wait<1>();
        } else {
            cp_wait<0>();
        }
        __syncthreads();

        const uint32_t st  = sbase + (uint32_t)(t & 1) * ST_BYTES;
        const uint32_t Ahs = st;
        const uint32_t Als = st + 16384u;
        const uint32_t Bhs = st + 32768u;
        const uint32_t Bls = st + 65536u;

        #pragma unroll
        for (int k16 = 0; k16 < 4; k16++) {
            const uint32_t koff = (uint32_t)(k16 * 32) + lcol;
            uint32_t ah[4][4], al[4][4];
            #pragma unroll
            for (int mt = 0; mt < 4; mt++) {
                uint32_t ro = SWZ128((uint32_t)((wm * 64 + mt * 16 + lrow) * 128) + koff);
                ldm_x4(ah[mt], Ahs + ro);
                ldm_x4(al[mt], Als + ro);
            }
            uint32_t bh[4][4], bl[4][4];
            #pragma unroll
            for (int ng = 0; ng < 4; ng++) {
                uint32_t ro = SWZ128((uint32_t)((wn * 64 + ng * 16 + lrow) * 128) + koff);
                ldm_x4(bh[ng], Bhs + ro);
                ldm_x4(bl[ng], Bls + ro);
            }
            #pragma unroll
            for (int mt = 0; mt < 4; mt++)
                #pragma unroll
                for (int j = 0; j < 8; j++) {
                    const int ng = j >> 1;
                    const int b0 = (j & 1) ? 1 : 0, b1 = (j & 1) ? 3 : 2;
                    mma_bf16(acc[mt][j], ah[mt], bh[ng][b0], bh[ng][b1]);
                    mma_bf16(acc[mt][j], al[mt], bh[ng][b0], bh[ng][b1]);
                    mma_bf16(acc[mt][j], ah[mt], bl[ng][b0], bl[ng][b1]);
                }
        }
        __syncthreads();
    }

    // Epilogue
    const int er = lane >> 2;
    const int ec = (lane & 3) * 2;
    if (Chi) {
        Chi += (size_t)blockIdx.z * sC;
        Clo += (size_t)blockIdx.z * sC;
        #pragma unroll
        for (int mt = 0; mt < 4; mt++) {
            const int rb = row0 + wm * 64 + mt * 16 + er;
            #pragma unroll
            for (int j = 0; j < 8; j++) {
                const int cb = col0 + wn * 64 + j * 8 + ec;
                #pragma unroll
                for (int h = 0; h < 2; h++) {
                    float vx = acc[mt][j][2 * h + 0];
                    float vy = acc[mt][j][2 * h + 1];
                    __nv_bfloat162 H, L;
                    H.x = __float2bfloat16(vx);
                    H.y = __float2bfloat16(vy);
                    L.x = __float2bfloat16(vx - __bfloat162float(H.x));
                    L.y = __float2bfloat16(vy - __bfloat162float(H.y));
                    const size_t o = (size_t)(rb + 8 * h) * ldC + cb;
                    *(__nv_bfloat162*)(Chi + o) = H;
                    *(__nv_bfloat162*)(Clo + o) = L;
                }
            }
        }
    } else {
        C += (size_t)blockIdx.z * sC;
        #pragma unroll
        for (int mt = 0; mt < 4; mt++) {
            const int rb = row0 + wm * 64 + mt * 16 + er;
            #pragma unroll
            for (int j = 0; j < 8; j++) {
                const int cb = col0 + wn * 64 + j * 8 + ec;
                float2 v0 = make_float2(alpha * acc[mt][j][0], alpha * acc[mt][j][1]);
                float2 v1 = make_float2(alpha * acc[mt][j][2], alpha * acc[mt][j][3]);
                *(float2*)(C + (size_t)rb * ldC + cb)       = v0;
                *(float2*)(C + (size_t)(rb + 8) * ldC + cb) = v1;
            }
        }
    }
}

// ===========================================================================
// fp32 -> (bf16 hi, bf16 lo) elementwise split, 4 elems/thread
// ===========================================================================
__global__ __launch_bounds__(256)
void split2(const float* __restrict__ src, __nv_bfloat16* __restrict__ hi,
            __nv_bfloat16* __restrict__ lo, size_t n4)
{
    size_t i = (size_t)blockIdx.x * 256 + threadIdx.x;
    if (i >= n4) return;
    float4 v = ((const float4*)src)[i];
    __nv_bfloat16 h0 = __float2bfloat16(v.x);
    __nv_bfloat16 h1 = __float2bfloat16(v.y);
    __nv_bfloat16 h2 = __float2bfloat16(v.z);
    __nv_bfloat16 h3 = __float2bfloat16(v.w);
    __nv_bfloat162 H0; H0.x = h0; H0.y = h1;
    __nv_bfloat162 H1; H1.x = h2; H1.y = h3;
    ((__nv_bfloat162*)hi)[2 * i + 0] = H0;
    ((__nv_bfloat162*)hi)[2 * i + 1] = H1;
    __nv_bfloat162 L0, L1;
    L0.x = __float2bfloat16(v.x - __bfloat162float(h0));
    L0.y = __float2bfloat16(v.y - __bfloat162float(h1));
    L1.x = __float2bfloat16(v.z - __bfloat162float(h2));
    L1.y = __float2bfloat16(v.w - __bfloat162float(h3));
    ((__nv_bfloat162*)lo)[2 * i + 0] = L0;
    ((__nv_bfloat162*)lo)[2 * i + 1] = L1;
}

// ===========================================================================
// bf16 [b,s,d] -> bf16 [b,d,s] transpose (64x64 tiles). grid.z = batch*2
// selects hi (z even) or lo (z odd) tensor pair.
// ===========================================================================
__global__ __launch_bounds__(256)
void transpose_bf16(const __nv_bfloat16* __restrict__ srcHi,
                    __nv_bfloat16* __restrict__ dstHi,
                    const __nv_bfloat16* __restrict__ srcLo,
                    __nv_bfloat16* __restrict__ dstLo)
{
    __shared__ __nv_bfloat16 t[64][65];
    const int z = blockIdx.z;
    const int b = z >> 1;
    const __nv_bfloat16* src = (z & 1) ? srcLo : srcHi;
    __nv_bfloat16*       dst = (z & 1) ? dstLo : dstHi;
    const int s0 = blockIdx.x * 64, d0 = blockIdx.y * 64;
    const int tid = threadIdx.x;
    src += (size_t)b * SEQ * DIM;
    dst += (size_t)b * DIM * SEQ;

    #pragma unroll
    for (int q = 0; q < 8; q++) {
        int i = tid + q * 256;
        int row = i >> 5, cp = i & 31;
        __nv_bfloat162 v = *(const __nv_bfloat162*)
            (src + (size_t)(s0 + row) * DIM + d0 + cp * 2);
        t[row][cp * 2 + 0] = v.x;
        t[row][cp * 2 + 1] = v.y;
    }
    __syncthreads();
    #pragma unroll
    for (int q = 0; q < 8; q++) {
        int i = tid + q * 256;
        int drow = i >> 5, sp = i & 31;
        __nv_bfloat162 o;
        o.x = t[sp * 2 + 0][drow];
        o.y = t[sp * 2 + 1][drow];
        *(__nv_bfloat162*)(dst + (size_t)(d0 + drow) * SEQ + s0 + sp * 2) = o;
    }
}

// ===========================================================================
// Row softmax (row held in registers) fused with bf16 hi/lo split output
// ===========================================================================
__global__ __launch_bounds__(256)
void softmax_split(const float* __restrict__ S, __nv_bfloat16* __restrict__ hi,
                   __nv_bfloat16* __restrict__ lo)
{
    __shared__ float red_m[8];
    __shared__ float red_s[8];
    const size_t base = (size_t)blockIdx.x * SEQ;
    const int tid  = threadIdx.x;
    const int wid  = tid >> 5;
    const int lane = tid & 31;

    const float4* row4 = (const float4*)(S + base);
    float4 v0 = row4[tid];
    float4 v1 = row4[tid + 256];

    float m = fmaxf(fmaxf(fmaxf(v0.x, v0.y), fmaxf(v0.z, v0.w)),
                    fmaxf(fmaxf(v1.x, v1.y), fmaxf(v1.z, v1.w)));
    #pragma unroll
    for (int o = 16; o > 0; o >>= 1) m = fmaxf(m, __shfl_xor_sync(~0u, m, o));
    if (lane == 0) red_m[wid] = m;
    __syncthreads();
    m = red_m[0];
    #pragma unroll
    for (int i = 1; i < 8; i++) m = fmaxf(m, red_m[i]);

    v0.x = __expf(v0.x - m); v0.y = __expf(v0.y - m);
    v0.z = __expf(v0.z - m); v0.w = __expf(v0.w - m);
    v1.x = __expf(v1.x - m); v1.y = __expf(v1.y - m);
    v1.z = __expf(v1.z - m); v1.w = __expf(v1.w - m);

    float s = v0.x + v0.y + v0.z + v0.w + v1.x + v1.y + v1.z + v1.w;
    #pragma unroll
    for (int o = 16; o > 0; o >>= 1) s += __shfl_xor_sync(~0u, s, o);
    if (lane == 0) red_s[wid] = s;
    __syncthreads();
    s = red_s[0];
    #pragma unroll
    for (int i = 1; i < 8; i++) s += red_s[i];
    const float inv = 1.f / s;

    auto emit = [&](float4 v, int c0) {
        float a0 = v.x * inv, a1 = v.y * inv, a2 = v.z * inv, a3 = v.w * inv;
        __nv_bfloat162 H0, H1, L0, L1;
        H0.x = __float2bfloat16(a0); H0.y = __float2bfloat16(a1);
        H1.x = __float2bfloat16(a2); H1.y = __float2bfloat16(a3);
        L0.x = __float2bfloat16(a0 - __bfloat162float(H0.x));
        L0.y = __float2bfloat16(a1 - __bfloat162float(H0.y));
        L1.x = __float2bfloat16(a2 - __bfloat162float(H1.x));
        L1.y = __float2bfloat16(a3 - __bfloat162float(H1.y));
        *(__nv_bfloat162*)(hi + base + c0)     = H0;
        *(__nv_bfloat162*)(hi + base + c0 + 2) = H1;
        *(__nv_bfloat162*)(lo + base + c0)     = L0;
        *(__nv_bfloat162*)(lo + base + c0 + 2) = L1;
    };
    emit(v0, tid * 4);
    emit(v1, (tid + 256) * 4);
}

// ===========================================================================
extern "C" void kernel_launch(void* const* d_in, const int* in_sizes, int n_in,
                              void* d_out, int out_size)
{
    const float* x  = (const float*)d_in[0];
    const float* Wq = (const float*)d_in[1];
    const float* Wk = (const float*)d_in[2];
    const float* Wv = (const float*)d_in[3];
    float* out = (float*)d_out;

    cudaFuncSetAttribute(hgemm3, cudaFuncAttributeMaxDynamicSharedMemorySize,
                         SMEM_GEMM);

    unsigned char* base;
    cudaGetSymbolAddress((void**)&base, g_scratch);

    __nv_bfloat16* xhi   = (__nv_bfloat16*)(base + O_XHI);
    __nv_bfloat16* xlo   = (__nv_bfloat16*)(base + O_XLO);
    __nv_bfloat16* whi   = (__nv_bfloat16*)(base + O_WHI);
    __nv_bfloat16* wlo   = (__nv_bfloat16*)(base + O_WLO);
    __nv_bfloat16* qkvhi = (__nv_bfloat16*)(base + O_QKVHI);
    __nv_bfloat16* qkvlo = (__nv_bfloat16*)(base + O_QKVLO);
    __nv_bfloat16* vthi  = (__nv_bfloat16*)(base + O_VTHI);
    __nv_bfloat16* vtlo  = (__nv_bfloat16*)(base + O_VTLO);
    float*         Sf    = (float*)(base + O_S);
    __nv_bfloat16* shi   = (__nv_bfloat16*)(base + O_SHI);
    __nv_bfloat16* slo   = (__nv_bfloat16*)(base + O_SLO);

    const float scale = 0.044194173824159216f;   // 1/sqrt(512)

    // 1. split x and the three weight matrices
    split2<<<(unsigned)(SZ_X / 4 / 256), 256>>>(x, xhi, xlo, SZ_X / 4);
    split2<<<DIM * DIM / 4 / 256, 256>>>(Wq, whi,                 wlo,                 DIM * DIM / 4);
    split2<<<DIM * DIM / 4 / 256, 256>>>(Wk, whi + DIM * DIM,     wlo + DIM * DIM,     DIM * DIM / 4);
    split2<<<DIM * DIM / 4 / 256, 256>>>(Wv, whi + 2 * DIM * DIM, wlo + 2 * DIM * DIM, DIM * DIM / 4);

    // 2. QKV projections, split bf16 epilogue (grid.z batches the 3 weights)
    {
        dim3 g(DIM / 256, MTOT / 128, 3);
        hgemm3<<<g, 256, SMEM_GEMM>>>(xhi, xlo, whi, wlo,
                                      nullptr, qkvhi, qkvlo,
                                      DIM, DIM, DIM, DIM / 64,
                                      0, (size_t)DIM * DIM, SZ_X, 1.0f);
    }

    // 3. transpose V (hi and lo) -> V^T
    {
        dim3 g(SEQ / 64, DIM / 64, BATCH * 2);
        transpose_bf16<<<g, 256>>>(qkvhi + 2 * SZ_X, vthi, qkvlo + 2 * SZ_X, vtlo);
    }

    // 4. scores = Q @ K^T * scale  (fp32 epilogue)
    {
        dim3 g(SEQ / 256, SEQ / 128, BATCH);
        hgemm3<<<g, 256, SMEM_GEMM>>>(qkvhi, qkvlo, qkvhi + SZ_X, qkvlo + SZ_X,
                                      Sf, nullptr, nullptr,
                                      DIM, DIM, SEQ, DIM / 64,
                                      (size_t)SEQ * DIM, (size_t)SEQ * DIM,
                                      (size_t)SEQ * SEQ, scale);
    }

    // 5. softmax + split
    softmax_split<<<BATCH * SEQ, 256>>>(Sf, shi, slo);

    // 6. out = attn @ V  (V pre-transposed -> NT form, fp32 epilogue)
    {
        dim3 g(DIM / 256, SEQ / 128, BATCH);
        hgemm3<<<g, 256, SMEM_GEMM>>>(shi, slo, vthi, vtlo,
                                      out, nullptr, nullptr,
                                      SEQ, SEQ, DIM, SEQ / 64,
                                      (size_t)SEQ * SEQ, (size_t)DIM * SEQ,
                                      (size_t)SEQ * DIM, 1.0f);
    }
}

// round 7
// speedup vs baseline: 2.0425x; 2.0425x over previous
#include <cuda_runtime.h>
#include <cuda_fp16.h>
#include <math.h>
#include <stdint.h>

#define BATCH 8
#define SEQ   2048
#define DIM   512
#define MTOT  (BATCH*SEQ)        // 16384

// ===========================================================================
// Scratch memory (single __device__ array; no allocation anywhere)
// ===========================================================================
#define SZ_X ((size_t)MTOT * DIM)                     // 8,388,608 elems
static const size_t O_XHI   = 0;                                // fp16 SZ_X
static const size_t O_XLO   = O_XHI   + SZ_X * 2;
static const size_t O_WHI   = O_XLO   + SZ_X * 2;               // fp16 3*DIM*DIM
static const size_t O_WLO   = O_WHI   + (size_t)3 * DIM * DIM * 2;
static const size_t O_QKVHI = O_WLO   + (size_t)3 * DIM * DIM * 2;  // fp16 3*SZ_X
static const size_t O_QKVLO = O_QKVHI + (size_t)3 * SZ_X * 2;
static const size_t O_VT    = O_QKVLO + (size_t)3 * SZ_X * 2;   // fp16 SZ_X (V^T)
static const size_t O_S     = O_VT    + SZ_X * 2;               // fp32 B*S*S
static const size_t O_SHI   = O_S     + (size_t)BATCH * SEQ * SEQ * 4;
static const size_t O_SLO   = O_SHI   + (size_t)BATCH * SEQ * SEQ * 2;
static const size_t SCRATCH_TOTAL = O_SLO + (size_t)BATCH * SEQ * SEQ * 2;

__device__ __align__(1024) unsigned char g_scratch[SCRATCH_TOTAL];

// ===========================================================================
// PTX helpers (arch-agnostic: cp.async / ldmatrix / mma.sync only)
// ===========================================================================
__device__ __forceinline__ uint32_t smem_u32(const void* p) {
    uint32_t a;
    asm("{ .reg .u64 t; cvta.to.shared.u64 t, %1; cvt.u32.u64 %0, t; }"
        : "=r"(a) : "l"(p));
    return a;
}

#define SWZ128(x) ((x) ^ (((x) >> 3) & 0x70))

__device__ __forceinline__ void cp16(uint32_t dst, const void* src) {
    asm volatile("cp.async.cg.shared.global [%0], [%1], 16;\n"
                 :: "r"(dst), "l"(src));
}
__device__ __forceinline__ void cp_commit() {
    asm volatile("cp.async.commit_group;\n" ::: "memory");
}
template <int N> __device__ __forceinline__ void cp_wait() {
    asm volatile("cp.async.wait_group %0;\n" :: "n"(N) : "memory");
}

__device__ __forceinline__ void ldm_x4(uint32_t* r, uint32_t addr) {
    asm volatile("ldmatrix.sync.aligned.m8n8.x4.shared.b16 {%0,%1,%2,%3}, [%4];"
                 : "=r"(r[0]), "=r"(r[1]), "=r"(r[2]), "=r"(r[3]) : "r"(addr));
}

__device__ __forceinline__ void mma_f16(float* c, const uint32_t* a,
                                        uint32_t b0, uint32_t b1) {
    asm volatile("mma.sync.aligned.m16n8k16.row.col.f32.f16.f16.f32 "
                 "{%0,%1,%2,%3}, {%4,%5,%6,%7}, {%8,%9}, {%0,%1,%2,%3};"
                 : "+f"(c[0]), "+f"(c[1]), "+f"(c[2]), "+f"(c[3])
                 : "r"(a[0]), "r"(a[1]), "r"(a[2]), "r"(a[3]), "r"(b0), "r"(b1));
}

// ===========================================================================
// HMMA GEMM:  C[M,N] = alpha * (Ahi@B^T + Alo@B^T)     (fp16 NT, fp32 accum)
// CTA 128x128, BK=64, 256 threads (8 warps, 32x64 warp tiles),
// double-buffered cp.async (2 x 48 KB stages: Ah 16K | Al 16K | B 16K).
// Epilogue: fp32*alpha if Chi==null, else fp16 hi/lo split.
// ===========================================================================
#define ST_BYTES 49152u
#define SMEM_GEMM (2 * 49152 + 1024)

__global__ __launch_bounds__(256, 1)
void hgemm2(const __half* __restrict__ Ahi,
            const __half* __restrict__ Alo,
            const __half* __restrict__ B,
            float* __restrict__ C,
            __half* __restrict__ Chi,
            __half* __restrict__ Clo,
            int ldA, int ldB, int ldC, int kTiles,
            size_t sA, size_t sB, size_t sC, float alpha)
{
    extern __shared__ char smem_raw[];
    const uint32_t sbase = (smem_u32(smem_raw) + 1023u) & ~1023u;

    const int tid  = threadIdx.x;
    const int wid  = tid >> 5;
    const int lane = tid & 31;
    const int wm   = wid & 3;      // 4 M-warps -> 32 rows each
    const int wn   = wid >> 2;     // 2 N-warps -> 64 cols each

    const int row0 = blockIdx.y * 128;
    const int col0 = blockIdx.x * 128;

    Ahi += (size_t)blockIdx.z * sA;  Alo += (size_t)blockIdx.z * sA;
    B   += (size_t)blockIdx.z * sB;

    float acc[2][8][4];
    #pragma unroll
    for (int mt = 0; mt < 2; mt++)
        #pragma unroll
        for (int j = 0; j < 8; j++)
            #pragma unroll
            for (int q = 0; q < 4; q++) acc[mt][j][q] = 0.f;

    // stage: [A_hi 16K][A_lo 16K][B 16K]
    auto load_stage = [&](int t) {
        const int kk = t * 64;
        const uint32_t st = sbase + (uint32_t)(t & 1) * ST_BYTES;
        #pragma unroll
        for (int q = 0; q < 4; q++) {                 // 128 rows x 8 chunks
            int idx = tid + q * 256;
            int rr = idx >> 3, cc = idx & 7;
            uint32_t d = SWZ128((uint32_t)(rr * 128 + cc * 16));
            size_t oa = (size_t)(row0 + rr) * ldA + kk + cc * 8;
            size_t ob = (size_t)(col0 + rr) * ldB + kk + cc * 8;
            cp16(st +          d, Ahi + oa);
            cp16(st + 16384u + d, Alo + oa);
            cp16(st + 32768u + d, B   + ob);
        }
        cp_commit();
    };

    load_stage(0);

    const uint32_t lrow = (uint32_t)(lane & 15);
    const uint32_t lcol = (uint32_t)((lane >> 4) * 16);

    for (int t = 0; t < kTiles; t++) {
        if (t + 1 < kTiles) {
            load_stage(t + 1);
            cp_wait<1>();
        } else {
            cp_wait<0>();
        }
        __syncthreads();

        const uint32_t st  = sbase + (uint32_t)(t & 1) * ST_BYTES;
        const uint32_t Ahs = st;
        const uint32_t Als = st + 16384u;
        const uint32_t Bs  = st + 32768u;

        #pragma unroll
        for (int k16 = 0; k16 < 4; k16++) {
            const uint32_t koff = (uint32_t)(k16 * 32) + lcol;
            uint32_t ah[2][4], al[2][4];
            #pragma unroll
            for (int mt = 0; mt < 2; mt++) {
                uint32_t ro = SWZ128((uint32_t)((wm * 32 + mt * 16 + lrow) * 128) + koff);
                ldm_x4(ah[mt], Ahs + ro);
                ldm_x4(al[mt], Als + ro);
            }
            uint32_t b[4][4];
            #pragma unroll
            for (int ng = 0; ng < 4; ng++) {
                uint32_t ro = SWZ128((uint32_t)((wn * 64 + ng * 16 + lrow) * 128) + koff);
                ldm_x4(b[ng], Bs + ro);
            }
            #pragma unroll
            for (int mt = 0; mt < 2; mt++)
                #pragma unroll
                for (int j = 0; j < 8; j++) {
                    const int ng = j >> 1;
                    const int b0 = (j & 1) ? 1 : 0, b1 = (j & 1) ? 3 : 2;
                    mma_f16(acc[mt][j], ah[mt], b[ng][b0], b[ng][b1]);
                    mma_f16(acc[mt][j], al[mt], b[ng][b0], b[ng][b1]);
                }
        }
        __syncthreads();
    }

    // Epilogue
    const int er = lane >> 2;
    const int ec = (lane & 3) * 2;
    if (Chi) {
        Chi += (size_t)blockIdx.z * sC;
        Clo += (size_t)blockIdx.z * sC;
        #pragma unroll
        for (int mt = 0; mt < 2; mt++) {
            const int rb = row0 + wm * 32 + mt * 16 + er;
            #pragma unroll
            for (int j = 0; j < 8; j++) {
                const int cb = col0 + wn * 64 + j * 8 + ec;
                #pragma unroll
                for (int h = 0; h < 2; h++) {
                    float vx = acc[mt][j][2 * h + 0];
                    float vy = acc[mt][j][2 * h + 1];
                    __half2 H, L;
                    H.x = __float2half(vx);
                    H.y = __float2half(vy);
                    L.x = __float2half(vx - __half2float(H.x));
                    L.y = __float2half(vy - __half2float(H.y));
                    const size_t o = (size_t)(rb + 8 * h) * ldC + cb;
                    *(__half2*)(Chi + o) = H;
                    *(__half2*)(Clo + o) = L;
                }
            }
        }
    } else {
        C += (size_t)blockIdx.z * sC;
        #pragma unroll
        for (int mt = 0; mt < 2; mt++) {
            const int rb = row0 + wm * 32 + mt * 16 + er;
            #pragma unroll
            for (int j = 0; j < 8; j++) {
                const int cb = col0 + wn * 64 + j * 8 + ec;
                float2 v0 = make_float2(alpha * acc[mt][j][0], alpha * acc[mt][j][1]);
                float2 v1 = make_float2(alpha * acc[mt][j][2], alpha * acc[mt][j][3]);
                *(float2*)(C + (size_t)rb * ldC + cb)       = v0;
                *(float2*)(C + (size_t)(rb + 8) * ldC + cb) = v1;
            }
        }
    }
}

// ===========================================================================
// fp32 -> (fp16 hi, fp16 lo) elementwise split, 4 elems/thread
// ===========================================================================
__global__ __launch_bounds__(256)
void split2h(const float* __restrict__ src, __half* __restrict__ hi,
             __half* __restrict__ lo, size_t n4)
{
    size_t i = (size_t)blockIdx.x * 256 + threadIdx.x;
    if (i >= n4) return;
    float4 v = ((const float4*)src)[i];
    __half h0 = __float2half(v.x);
    __half h1 = __float2half(v.y);
    __half h2 = __float2half(v.z);
    __half h3 = __float2half(v.w);
    __half2 H0; H0.x = h0; H0.y = h1;
    __half2 H1; H1.x = h2; H1.y = h3;
    ((__half2*)hi)[2 * i + 0] = H0;
    ((__half2*)hi)[2 * i + 1] = H1;
    __half2 L0, L1;
    L0.x = __float2half(v.x - __half2float(h0));
    L0.y = __float2half(v.y - __half2float(h1));
    L1.x = __float2half(v.z - __half2float(h2));
    L1.y = __float2half(v.w - __half2float(h3));
    ((__half2*)lo)[2 * i + 0] = L0;
    ((__half2*)lo)[2 * i + 1] = L1;
}

// ===========================================================================
// fp16 [b,s,d] -> fp16 [b,d,s] transpose (64x64 tiles), grid.z = batch
// ===========================================================================
__global__ __launch_bounds__(256)
void transpose_h(const __half* __restrict__ src, __half* __restrict__ dst)
{
    __shared__ __half t[64][65];
    const int b  = blockIdx.z;
    const int s0 = blockIdx.x * 64, d0 = blockIdx.y * 64;
    const int tid = threadIdx.x;
    src += (size_t)b * SEQ * DIM;
    dst += (size_t)b * DIM * SEQ;

    #pragma unroll
    for (int q = 0; q < 8; q++) {
        int i = tid + q * 256;
        int row = i >> 5, cp = i & 31;
        __half2 v = *(const __half2*)(src + (size_t)(s0 + row) * DIM + d0 + cp * 2);
        t[row][cp * 2 + 0] = v.x;
        t[row][cp * 2 + 1] = v.y;
    }
    __syncthreads();
    #pragma unroll
    for (int q = 0; q < 8; q++) {
        int i = tid + q * 256;
        int drow = i >> 5, sp = i & 31;
        __half2 o;
        o.x = t[sp * 2 + 0][drow];
        o.y = t[sp * 2 + 1][drow];
        *(__half2*)(dst + (size_t)(d0 + drow) * SEQ + s0 + sp * 2) = o;
    }
}

// ===========================================================================
// Row softmax (registers) fused with fp16 hi/lo split output
// ===========================================================================
__global__ __launch_bounds__(256)
void softmax_split(const float* __restrict__ S, __half* __restrict__ hi,
                   __half* __restrict__ lo)
{
    __shared__ float red_m[8];
    __shared__ float red_s[8];
    const size_t base = (size_t)blockIdx.x * SEQ;
    const int tid  = threadIdx.x;
    const int wid  = tid >> 5;
    const int lane = tid & 31;

    const float4* row4 = (const float4*)(S + base);
    float4 v0 = row4[tid];
    float4 v1 = row4[tid + 256];

    float m = fmaxf(fmaxf(fmaxf(v0.x, v0.y), fmaxf(v0.z, v0.w)),
                    fmaxf(fmaxf(v1.x, v1.y), fmaxf(v1.z, v1.w)));
    #pragma unroll
    for (int o = 16; o > 0; o >>= 1) m = fmaxf(m, __shfl_xor_sync(~0u, m, o));
    if (lane == 0) red_m[wid] = m;
    __syncthreads();
    m = red_m[0];
    #pragma unroll
    for (int i = 1; i < 8; i++) m = fmaxf(m, red_m[i]);

    v0.x = __expf(v0.x - m); v0.y = __expf(v0.y - m);
    v0.z = __expf(v0.z - m); v0.w = __expf(v0.w - m);
    v1.x = __expf(v1.x - m); v1.y = __expf(v1.y - m);
    v1.z = __expf(v1.z - m); v1.w = __expf(v1.w - m);

    float s = v0.x + v0.y + v0.z + v0.w + v1.x + v1.y + v1.z + v1.w;
    #pragma unroll
    for (int o = 16; o > 0; o >>= 1) s += __shfl_xor_sync(~0u, s, o);
    if (lane == 0) red_s[wid] = s;
    __syncthreads();
    s = red_s[0];
    #pragma unroll
    for (int i = 1; i < 8; i++) s += red_s[i];
    const float inv = 1.f / s;

    auto emit = [&](float4 v, int c0) {
        float a0 = v.x * inv, a1 = v.y * inv, a2 = v.z * inv, a3 = v.w * inv;
        __half2 H0, H1, L0, L1;
        H0.x = __float2half(a0); H0.y = __float2half(a1);
        H1.x = __float2half(a2); H1.y = __float2half(a3);
        L0.x = __float2half(a0 - __half2float(H0.x));
        L0.y = __float2half(a1 - __half2float(H0.y));
        L1.x = __float2half(a2 - __half2float(H1.x));
        L1.y = __float2half(a3 - __half2float(H1.y));
        *(__half2*)(hi + base + c0)     = H0;
        *(__half2*)(hi + base + c0 + 2) = H1;
        *(__half2*)(lo + base + c0)     = L0;
        *(__half2*)(lo + base + c0 + 2) = L1;
    };
    emit(v0, tid * 4);
    emit(v1, (tid + 256) * 4);
}

// ===========================================================================
extern "C" void kernel_launch(void* const* d_in, const int* in_sizes, int n_in,
                              void* d_out, int out_size)
{
    const float* x  = (const float*)d_in[0];
    const float* Wq = (const float*)d_in[1];
    const float* Wk = (const float*)d_in[2];
    const float* Wv = (const float*)d_in[3];
    float* out = (float*)d_out;

    cudaFuncSetAttribute(hgemm2, cudaFuncAttributeMaxDynamicSharedMemorySize,
                         SMEM_GEMM);

    unsigned char* base;
    cudaGetSymbolAddress((void**)&base, g_scratch);

    __half* xhi   = (__half*)(base + O_XHI);
    __half* xlo   = (__half*)(base + O_XLO);
    __half* whi   = (__half*)(base + O_WHI);
    __half* wlo   = (__half*)(base + O_WLO);
    __half* qkvhi = (__half*)(base + O_QKVHI);
    __half* qkvlo = (__half*)(base + O_QKVLO);
    __half* vt    = (__half*)(base + O_VT);
    float*  Sf    = (float*)(base + O_S);
    __half* shi   = (__half*)(base + O_SHI);
    __half* slo   = (__half*)(base + O_SLO);

    const float scale = 0.044194173824159216f;   // 1/sqrt(512)

    // 1. split x (A-side, hi+lo used); W quantized fp16 (B-side, hi used)
    split2h<<<(unsigned)(SZ_X / 4 / 256), 256>>>(x, xhi, xlo, SZ_X / 4);
    split2h<<<DIM * DIM / 4 / 256, 256>>>(Wq, whi,                 wlo,                 DIM * DIM / 4);
    split2h<<<DIM * DIM / 4 / 256, 256>>>(Wk, whi + DIM * DIM,     wlo + DIM * DIM,     DIM * DIM / 4);
    split2h<<<DIM * DIM / 4 / 256, 256>>>(Wv, whi + 2 * DIM * DIM, wlo + 2 * DIM * DIM, DIM * DIM / 4);

    // 2. QKV projections, split fp16 epilogue (grid.z batches the 3 weights)
    {
        dim3 g(DIM / 128, MTOT / 128, 3);
        hgemm2<<<g, 256, SMEM_GEMM>>>(xhi, xlo, whi,
                                      nullptr, qkvhi, qkvlo,
                                      DIM, DIM, DIM, DIM / 64,
                                      0, (size_t)DIM * DIM, SZ_X, 1.0f);
    }

    // 3. transpose V (hi only; V is B-side single) -> V^T
    {
        dim3 g(SEQ / 64, DIM / 64, BATCH);
        transpose_h<<<g, 256>>>(qkvhi + 2 * SZ_X, vt);
    }

    // 4. scores = Q @ K^T * scale  (Q split A-side, K single B-side)
    {
        dim3 g(SEQ / 128, SEQ / 128, BATCH);
        hgemm2<<<g, 256, SMEM_GEMM>>>(qkvhi, qkvlo, qkvhi + SZ_X,
                                      Sf, nullptr, nullptr,
                                      DIM, DIM, SEQ, DIM / 64,
                                      (size_t)SEQ * DIM, (size_t)SEQ * DIM,
                                      (size_t)SEQ * SEQ, scale);
    }

    // 5. softmax + split
    softmax_split<<<BATCH * SEQ, 256>>>(Sf, shi, slo);

    // 6. out = attn @ V  (attn split A-side, V^T single B-side)
    {
        dim3 g(DIM / 128, SEQ / 128, BATCH);
        hgemm2<<<g, 256, SMEM_GEMM>>>(shi, slo, vt,
                                      out, nullptr, nullptr,
                                      SEQ, SEQ, DIM, SEQ / 64,
                                      (size_t)SEQ * SEQ, (size_t)DIM * SEQ,
                                      (size_t)SEQ * DIM, 1.0f);
    }
}

// round 8
// speedup vs baseline: 2.4214x; 1.1855x over previous
#include <cuda_runtime.h>
#include <cuda_fp16.h>
#include <math.h>
#include <stdint.h>

#define BATCH 8
#define SEQ   2048
#define DIM   512
#define MTOT  (BATCH*SEQ)        // 16384

// ===========================================================================
// Scratch memory (single __device__ array; no allocation anywhere)
// ===========================================================================
#define SZ_X ((size_t)MTOT * DIM)                     // 8,388,608 elems
static const size_t O_XHI   = 0;                                // fp16 SZ_X
static const size_t O_XLO   = O_XHI   + SZ_X * 2;
static const size_t O_WHI   = O_XLO   + SZ_X * 2;               // fp16 3*DIM*DIM
static const size_t O_WLO   = O_WHI   + (size_t)3 * DIM * DIM * 2;
static const size_t O_QKVHI = O_WLO   + (size_t)3 * DIM * DIM * 2;  // fp16 3*SZ_X
static const size_t O_QKVLO = O_QKVHI + (size_t)3 * SZ_X * 2;
static const size_t O_VT    = O_QKVLO + (size_t)3 * SZ_X * 2;   // fp16 SZ_X (V^T)
static const size_t O_S     = O_VT    + SZ_X * 2;               // fp32 B*S*S
static const size_t O_SHI   = O_S     + (size_t)BATCH * SEQ * SEQ * 4;
static const size_t SCRATCH_TOTAL = O_SHI + (size_t)BATCH * SEQ * SEQ * 2;

__device__ __align__(1024) unsigned char g_scratch[SCRATCH_TOTAL];

// ===========================================================================
// PTX helpers (arch-agnostic: cp.async / ldmatrix / mma.sync only)
// ===========================================================================
__device__ __forceinline__ uint32_t smem_u32(const void* p) {
    uint32_t a;
    asm("{ .reg .u64 t; cvta.to.shared.u64 t, %1; cvt.u32.u64 %0, t; }"
        : "=r"(a) : "l"(p));
    return a;
}

#define SWZ128(x) ((x) ^ (((x) >> 3) & 0x70))

__device__ __forceinline__ void cp16(uint32_t dst, const void* src) {
    asm volatile("cp.async.cg.shared.global [%0], [%1], 16;\n"
                 :: "r"(dst), "l"(src));
}
__device__ __forceinline__ void cp_commit() {
    asm volatile("cp.async.commit_group;\n" ::: "memory");
}
template <int N> __device__ __forceinline__ void cp_wait() {
    asm volatile("cp.async.wait_group %0;\n" :: "n"(N) : "memory");
}

__device__ __forceinline__ void ldm_x4(uint32_t* r, uint32_t addr) {
    asm volatile("ldmatrix.sync.aligned.m8n8.x4.shared.b16 {%0,%1,%2,%3}, [%4];"
                 : "=r"(r[0]), "=r"(r[1]), "=r"(r[2]), "=r"(r[3]) : "r"(addr));
}

__device__ __forceinline__ void mma_f16(float* c, const uint32_t* a,
                                        uint32_t b0, uint32_t b1) {
    asm volatile("mma.sync.aligned.m16n8k16.row.col.f32.f16.f16.f32 "
                 "{%0,%1,%2,%3}, {%4,%5,%6,%7}, {%8,%9}, {%0,%1,%2,%3};"
                 : "+f"(c[0]), "+f"(c[1]), "+f"(c[2]), "+f"(c[3])
                 : "r"(a[0]), "r"(a[1]), "r"(a[2]), "r"(a[3]), "r"(b0), "r"(b1));
}

// ===========================================================================
// 2-term HMMA GEMM:  C = alpha * (Ahi@B^T + Alo@B^T)   (fp16 NT, fp32 accum)
// CTA 128x128, BK=64, 256 threads, 8 warps x (32M x 64N) tiles,
// 2 x 48 KB cp.async stages.  Epilogue: fp32*alpha or fp16 hi/lo split.
// ===========================================================================
#define ST2_BYTES 49152u
#define SMEM_GEMM2 (2 * 49152 + 1024)

__global__ __launch_bounds__(256, 1)
void hgemm2(const __half* __restrict__ Ahi,
            const __half* __restrict__ Alo,
            const __half* __restrict__ B,
            float* __restrict__ C,
            __half* __restrict__ Chi,
            __half* __restrict__ Clo,
            int ldA, int ldB, int ldC, int kTiles,
            size_t sA, size_t sB, size_t sC, float alpha)
{
    extern __shared__ char smem_raw[];
    const uint32_t sbase = (smem_u32(smem_raw) + 1023u) & ~1023u;

    const int tid  = threadIdx.x;
    const int wid  = tid >> 5;
    const int lane = tid & 31;
    const int wm   = wid & 3;
    const int wn   = wid >> 2;

    const int row0 = blockIdx.y * 128;
    const int col0 = blockIdx.x * 128;

    Ahi += (size_t)blockIdx.z * sA;  Alo += (size_t)blockIdx.z * sA;
    B   += (size_t)blockIdx.z * sB;

    float acc[2][8][4];
    #pragma unroll
    for (int mt = 0; mt < 2; mt++)
        #pragma unroll
        for (int j = 0; j < 8; j++)
            #pragma unroll
            for (int q = 0; q < 4; q++) acc[mt][j][q] = 0.f;

    auto load_stage = [&](int t) {
        const int kk = t * 64;
        const uint32_t st = sbase + (uint32_t)(t & 1) * ST2_BYTES;
        #pragma unroll
        for (int q = 0; q < 4; q++) {
            int idx = tid + q * 256;
            int rr = idx >> 3, cc = idx & 7;
            uint32_t d = SWZ128((uint32_t)(rr * 128 + cc * 16));
            size_t oa = (size_t)(row0 + rr) * ldA + kk + cc * 8;
            size_t ob = (size_t)(col0 + rr) * ldB + kk + cc * 8;
            cp16(st +          d, Ahi + oa);
            cp16(st + 16384u + d, Alo + oa);
            cp16(st + 32768u + d, B   + ob);
        }
        cp_commit();
    };

    load_stage(0);

    const uint32_t lrow = (uint32_t)(lane & 15);
    const uint32_t lcol = (uint32_t)((lane >> 4) * 16);

    for (int t = 0; t < kTiles; t++) {
        if (t + 1 < kTiles) {
            load_stage(t + 1);
            cp_wait<1>();
        } else {
            cp_wait<0>();
        }
        __syncthreads();

        const uint32_t st  = sbase + (uint32_t)(t & 1) * ST2_BYTES;
        const uint32_t Ahs = st;
        const uint32_t Als = st + 16384u;
        const uint32_t Bs  = st + 32768u;

        #pragma unroll
        for (int k16 = 0; k16 < 4; k16++) {
            const uint32_t koff = (uint32_t)(k16 * 32) + lcol;
            uint32_t ah[2][4], al[2][4];
            #pragma unroll
            for (int mt = 0; mt < 2; mt++) {
                uint32_t ro = SWZ128((uint32_t)((wm * 32 + mt * 16 + lrow) * 128) + koff);
                ldm_x4(ah[mt], Ahs + ro);
                ldm_x4(al[mt], Als + ro);
            }
            uint32_t b[4][4];
            #pragma unroll
            for (int ng = 0; ng < 4; ng++) {
                uint32_t ro = SWZ128((uint32_t)((wn * 64 + ng * 16 + lrow) * 128) + koff);
                ldm_x4(b[ng], Bs + ro);
            }
            #pragma unroll
            for (int mt = 0; mt < 2; mt++)
                #pragma unroll
                for (int j = 0; j < 8; j++) {
                    const int ng = j >> 1;
                    const int b0 = (j & 1) ? 1 : 0, b1 = (j & 1) ? 3 : 2;
                    mma_f16(acc[mt][j], ah[mt], b[ng][b0], b[ng][b1]);
                    mma_f16(acc[mt][j], al[mt], b[ng][b0], b[ng][b1]);
                }
        }
        __syncthreads();
    }

    const int er = lane >> 2;
    const int ec = (lane & 3) * 2;
    if (Chi) {
        Chi += (size_t)blockIdx.z * sC;
        Clo += (size_t)blockIdx.z * sC;
        #pragma unroll
        for (int mt = 0; mt < 2; mt++) {
            const int rb = row0 + wm * 32 + mt * 16 + er;
            #pragma unroll
            for (int j = 0; j < 8; j++) {
                const int cb = col0 + wn * 64 + j * 8 + ec;
                #pragma unroll
                for (int h = 0; h < 2; h++) {
                    float vx = acc[mt][j][2 * h + 0];
                    float vy = acc[mt][j][2 * h + 1];
                    __half2 H, L;
                    H.x = __float2half(vx);
                    H.y = __float2half(vy);
                    L.x = __float2half(vx - __half2float(H.x));
                    L.y = __float2half(vy - __half2float(H.y));
                    const size_t o = (size_t)(rb + 8 * h) * ldC + cb;
                    *(__half2*)(Chi + o) = H;
                    *(__half2*)(Clo + o) = L;
                }
            }
        }
    } else {
        C += (size_t)blockIdx.z * sC;
        #pragma unroll
        for (int mt = 0; mt < 2; mt++) {
            const int rb = row0 + wm * 32 + mt * 16 + er;
            #pragma unroll
            for (int j = 0; j < 8; j++) {
                const int cb = col0 + wn * 64 + j * 8 + ec;
                float2 v0 = make_float2(alpha * acc[mt][j][0], alpha * acc[mt][j][1]);
                float2 v1 = make_float2(alpha * acc[mt][j][2], alpha * acc[mt][j][3]);
                *(float2*)(C + (size_t)rb * ldC + cb)       = v0;
                *(float2*)(C + (size_t)(rb + 8) * ldC + cb) = v1;
            }
        }
    }
}

// ===========================================================================
// 1-term HMMA GEMM:  C = A@B^T  (fp16 NT, fp32 accum, fp32 epilogue)
// CTA 128x128, BK=64, 2 x 32 KB stages.
// ===========================================================================
#define ST1_BYTES 32768u
#define SMEM_GEMM1 (2 * 32768 + 1024)

__global__ __launch_bounds__(256, 1)
void hgemm1(const __half* __restrict__ A,
            const __half* __restrict__ B,
            float* __restrict__ C,
            int ldA, int ldB, int ldC, int kTiles,
            size_t sA, size_t sB, size_t sC)
{
    extern __shared__ char smem_raw[];
    const uint32_t sbase = (smem_u32(smem_raw) + 1023u) & ~1023u;

    const int tid  = threadIdx.x;
    const int wid  = tid >> 5;
    const int lane = tid & 31;
    const int wm   = wid & 3;
    const int wn   = wid >> 2;

    const int row0 = blockIdx.y * 128;
    const int col0 = blockIdx.x * 128;

    A += (size_t)blockIdx.z * sA;
    B += (size_t)blockIdx.z * sB;

    float acc[2][8][4];
    #pragma unroll
    for (int mt = 0; mt < 2; mt++)
        #pragma unroll
        for (int j = 0; j < 8; j++)
            #pragma unroll
            for (int q = 0; q < 4; q++) acc[mt][j][q] = 0.f;

    auto load_stage = [&](int t) {
        const int kk = t * 64;
        const uint32_t st = sbase + (uint32_t)(t & 1) * ST1_BYTES;
        #pragma unroll
        for (int q = 0; q < 4; q++) {
            int idx = tid + q * 256;
            int rr = idx >> 3, cc = idx & 7;
            uint32_t d = SWZ128((uint32_t)(rr * 128 + cc * 16));
            cp16(st +          d, A + (size_t)(row0 + rr) * ldA + kk + cc * 8);
            cp16(st + 16384u + d, B + (size_t)(col0 + rr) * ldB + kk + cc * 8);
        }
        cp_commit();
    };

    load_stage(0);

    const uint32_t lrow = (uint32_t)(lane & 15);
    const uint32_t lcol = (uint32_t)((lane >> 4) * 16);

    for (int t = 0; t < kTiles; t++) {
        if (t + 1 < kTiles) {
            load_stage(t + 1);
            cp_wait<1>();
        } else {
            cp_wait<0>();
        }
        __syncthreads();

        const uint32_t st = sbase + (uint32_t)(t & 1) * ST1_BYTES;
        const uint32_t As = st;
        const uint32_t Bs = st + 16384u;

        #pragma unroll
        for (int k16 = 0; k16 < 4; k16++) {
            const uint32_t koff = (uint32_t)(k16 * 32) + lcol;
            uint32_t a[2][4];
            #pragma unroll
            for (int mt = 0; mt < 2; mt++)
                ldm_x4(a[mt], As + SWZ128((uint32_t)((wm * 32 + mt * 16 + lrow) * 128) + koff));
            uint32_t b[4][4];
            #pragma unroll
            for (int ng = 0; ng < 4; ng++)
                ldm_x4(b[ng], Bs + SWZ128((uint32_t)((wn * 64 + ng * 16 + lrow) * 128) + koff));
            #pragma unroll
            for (int mt = 0; mt < 2; mt++)
                #pragma unroll
                for (int j = 0; j < 8; j++) {
                    const int ng = j >> 1;
                    mma_f16(acc[mt][j], a[mt], b[ng][(j & 1) ? 1 : 0], b[ng][(j & 1) ? 3 : 2]);
                }
        }
        __syncthreads();
    }

    C += (size_t)blockIdx.z * sC;
    const int er = lane >> 2;
    const int ec = (lane & 3) * 2;
    #pragma unroll
    for (int mt = 0; mt < 2; mt++) {
        const int rb = row0 + wm * 32 + mt * 16 + er;
        #pragma unroll
        for (int j = 0; j < 8; j++) {
            const int cb = col0 + wn * 64 + j * 8 + ec;
            *(float2*)(C + (size_t)rb * ldC + cb)       = make_float2(acc[mt][j][0], acc[mt][j][1]);
            *(float2*)(C + (size_t)(rb + 8) * ldC + cb) = make_float2(acc[mt][j][2], acc[mt][j][3]);
        }
    }
}

// ===========================================================================
// fp32 -> (fp16 hi, fp16 lo) elementwise split, 4 elems/thread
// ===========================================================================
__global__ __launch_bounds__(256)
void split2h(const float* __restrict__ src, __half* __restrict__ hi,
             __half* __restrict__ lo, size_t n4)
{
    size_t i = (size_t)blockIdx.x * 256 + threadIdx.x;
    if (i >= n4) return;
    float4 v = ((const float4*)src)[i];
    __half h0 = __float2half(v.x);
    __half h1 = __float2half(v.y);
    __half h2 = __float2half(v.z);
    __half h3 = __float2half(v.w);
    __half2 H0; H0.x = h0; H0.y = h1;
    __half2 H1; H1.x = h2; H1.y = h3;
    ((__half2*)hi)[2 * i + 0] = H0;
    ((__half2*)hi)[2 * i + 1] = H1;
    __half2 L0, L1;
    L0.x = __float2half(v.x - __half2float(h0));
    L0.y = __float2half(v.y - __half2float(h1));
    L1.x = __float2half(v.z - __half2float(h2));
    L1.y = __float2half(v.w - __half2float(h3));
    ((__half2*)lo)[2 * i + 0] = L0;
    ((__half2*)lo)[2 * i + 1] = L1;
}

// ===========================================================================
// fp16 [b,s,d] -> fp16 [b,d,s] transpose (64x64 tiles), grid.z = batch
// ===========================================================================
__global__ __launch_bounds__(256)
void transpose_h(const __half* __restrict__ src, __half* __restrict__ dst)
{
    __shared__ __half t[64][65];
    const int b  = blockIdx.z;
    const int s0 = blockIdx.x * 64, d0 = blockIdx.y * 64;
    const int tid = threadIdx.x;
    src += (size_t)b * SEQ * DIM;
    dst += (size_t)b * DIM * SEQ;

    #pragma unroll
    for (int q = 0; q < 8; q++) {
        int i = tid + q * 256;
        int row = i >> 5, cp = i & 31;
        __half2 v = *(const __half2*)(src + (size_t)(s0 + row) * DIM + d0 + cp * 2);
        t[row][cp * 2 + 0] = v.x;
        t[row][cp * 2 + 1] = v.y;
    }
    __syncthreads();
    #pragma unroll
    for (int q = 0; q < 8; q++) {
        int i = tid + q * 256;
        int drow = i >> 5, sp = i & 31;
        __half2 o;
        o.x = t[sp * 2 + 0][drow];
        o.y = t[sp * 2 + 1][drow];
        *(__half2*)(dst + (size_t)(d0 + drow) * SEQ + s0 + sp * 2) = o;
    }
}

// ===========================================================================
// Row softmax (registers), fp16 output (hi only)
// ===========================================================================
__global__ __launch_bounds__(256)
void softmax_h(const float* __restrict__ S, __half* __restrict__ hi)
{
    __shared__ float red_m[8];
    __shared__ float red_s[8];
    const size_t base = (size_t)blockIdx.x * SEQ;
    const int tid  = threadIdx.x;
    const int wid  = tid >> 5;
    const int lane = tid & 31;

    const float4* row4 = (const float4*)(S + base);
    float4 v0 = row4[tid];
    float4 v1 = row4[tid + 256];

    float m = fmaxf(fmaxf(fmaxf(v0.x, v0.y), fmaxf(v0.z, v0.w)),
                    fmaxf(fmaxf(v1.x, v1.y), fmaxf(v1.z, v1.w)));
    #pragma unroll
    for (int o = 16; o > 0; o >>= 1) m = fmaxf(m, __shfl_xor_sync(~0u, m, o));
    if (lane == 0) red_m[wid] = m;
    __syncthreads();
    m = red_m[0];
    #pragma unroll
    for (int i = 1; i < 8; i++) m = fmaxf(m, red_m[i]);

    v0.x = __expf(v0.x - m); v0.y = __expf(v0.y - m);
    v0.z = __expf(v0.z - m); v0.w = __expf(v0.w - m);
    v1.x = __expf(v1.x - m); v1.y = __expf(v1.y - m);
    v1.z = __expf(v1.z - m); v1.w = __expf(v1.w - m);

    float s = v0.x + v0.y + v0.z + v0.w + v1.x + v1.y + v1.z + v1.w;
    #pragma unroll
    for (int o = 16; o > 0; o >>= 1) s += __shfl_xor_sync(~0u, s, o);
    if (lane == 0) red_s[wid] = s;
    __syncthreads();
    s = red_s[0];
    #pragma unroll
    for (int i = 1; i < 8; i++) s += red_s[i];
    const float inv = 1.f / s;

    auto emit = [&](float4 v, int c0) {
        __half2 H0, H1;
        H0.x = __float2half(v.x * inv); H0.y = __float2half(v.y * inv);
        H1.x = __float2half(v.z * inv); H1.y = __float2half(v.w * inv);
        *(__half2*)(hi + base + c0)     = H0;
        *(__half2*)(hi + base + c0 + 2) = H1;
    };
    emit(v0, tid * 4);
    emit(v1, (tid + 256) * 4);
}

// ===========================================================================
extern "C" void kernel_launch(void* const* d_in, const int* in_sizes, int n_in,
                              void* d_out, int out_size)
{
    const float* x  = (const float*)d_in[0];
    const float* Wq = (const float*)d_in[1];
    const float* Wk = (const float*)d_in[2];
    const float* Wv = (const float*)d_in[3];
    float* out = (float*)d_out;

    cudaFuncSetAttribute(hgemm2, cudaFuncAttributeMaxDynamicSharedMemorySize, SMEM_GEMM2);
    cudaFuncSetAttribute(hgemm1, cudaFuncAttributeMaxDynamicSharedMemorySize, SMEM_GEMM1);

    unsigned char* base;
    cudaGetSymbolAddress((void**)&base, g_scratch);

    __half* xhi   = (__half*)(base + O_XHI);
    __half* xlo   = (__half*)(base + O_XLO);
    __half* whi   = (__half*)(base + O_WHI);
    __half* wlo   = (__half*)(base + O_WLO);
    __half* qkvhi = (__half*)(base + O_QKVHI);
    __half* qkvlo = (__half*)(base + O_QKVLO);
    __half* vt    = (__half*)(base + O_VT);
    float*  Sf    = (float*)(base + O_S);
    __half* shi   = (__half*)(base + O_SHI);

    const float scale = 0.044194173824159216f;   // 1/sqrt(512)

    // 1. split x (A-side hi+lo); W quantized fp16 (B-side, hi used)
    split2h<<<(unsigned)(SZ_X / 4 / 256), 256>>>(x, xhi, xlo, SZ_X / 4);
    split2h<<<DIM * DIM / 4 / 256, 256>>>(Wq, whi,                 wlo,                 DIM * DIM / 4);
    split2h<<<DIM * DIM / 4 / 256, 256>>>(Wk, whi + DIM * DIM,     wlo + DIM * DIM,     DIM * DIM / 4);
    split2h<<<DIM * DIM / 4 / 256, 256>>>(Wv, whi + 2 * DIM * DIM, wlo + 2 * DIM * DIM, DIM * DIM / 4);

    // 2. QKV projections, split fp16 epilogue (grid.z batches the 3 weights)
    {
        dim3 g(DIM / 128, MTOT / 128, 3);
        hgemm2<<<g, 256, SMEM_GEMM2>>>(xhi, xlo, whi,
                                       nullptr, qkvhi, qkvlo,
                                       DIM, DIM, DIM, DIM / 64,
                                       0, (size_t)DIM * DIM, SZ_X, 1.0f);
    }

    // 3. transpose V (hi only) -> V^T
    {
        dim3 g(SEQ / 64, DIM / 64, BATCH);
        transpose_h<<<g, 256>>>(qkvhi + 2 * SZ_X, vt);
    }

    // 4. scores = Q @ K^T * scale  (Q split 2-term, K single)
    {
        dim3 g(SEQ / 128, SEQ / 128, BATCH);
        hgemm2<<<g, 256, SMEM_GEMM2>>>(qkvhi, qkvlo, qkvhi + SZ_X,
                                       Sf, nullptr, nullptr,
                                       DIM, DIM, SEQ, DIM / 64,
                                       (size_t)SEQ * DIM, (size_t)SEQ * DIM,
                                       (size_t)SEQ * SEQ, scale);
    }

    // 5. softmax -> fp16 attn (hi only)
    softmax_h<<<BATCH * SEQ, 256>>>(Sf, shi);

    // 6. out = attn @ V  (single-term fp16 GEMM)
    {
        dim3 g(DIM / 128, SEQ / 128, BATCH);
        hgemm1<<<g, 256, SMEM_GEMM1>>>(shi, vt, out,
                                       SEQ, SEQ, DIM, SEQ / 64,
                                       (size_t)SEQ * SEQ, (size_t)DIM * SEQ,
                                       (size_t)SEQ * DIM);
    }
}

// round 9
// speedup vs baseline: 4.1374x; 1.7087x over previous
#include <cuda_runtime.h>
#include <cuda_fp16.h>
#include <math.h>
#include <stdint.h>

#define BATCH 8
#define SEQ   2048
#define DIM   512
#define MTOT  (BATCH*SEQ)        // 16384

// ===========================================================================
// Scratch memory (single __device__ array; no allocation anywhere)
// ===========================================================================
#define SZ_X ((size_t)MTOT * DIM)                     // 8,388,608 elems
static const size_t O_XH   = 0;                                 // fp16 SZ_X
static const size_t O_WH   = O_XH  + SZ_X * 2;                  // fp16 3*DIM*DIM
static const size_t O_QKVH = O_WH  + (size_t)3 * DIM * DIM * 2; // fp16 3*SZ_X
static const size_t O_VT   = O_QKVH + (size_t)3 * SZ_X * 2;     // fp16 SZ_X (V^T)
static const size_t O_S    = O_VT  + SZ_X * 2;                  // fp32 B*S*S
static const size_t O_SH   = O_S   + (size_t)BATCH * SEQ * SEQ * 4;
static const size_t SCRATCH_TOTAL = O_SH + (size_t)BATCH * SEQ * SEQ * 2;

__device__ __align__(1024) unsigned char g_scratch[SCRATCH_TOTAL];

// ===========================================================================
// PTX helpers (arch-agnostic: cp.async / ldmatrix / mma.sync only)
// ===========================================================================
__device__ __forceinline__ uint32_t smem_u32(const void* p) {
    uint32_t a;
    asm("{ .reg .u64 t; cvta.to.shared.u64 t, %1; cvt.u32.u64 %0, t; }"
        : "=r"(a) : "l"(p));
    return a;
}

#define SWZ128(x) ((x) ^ (((x) >> 3) & 0x70))

__device__ __forceinline__ void cp16(uint32_t dst, const void* src) {
    asm volatile("cp.async.cg.shared.global [%0], [%1], 16;\n"
                 :: "r"(dst), "l"(src));
}
__device__ __forceinline__ void cp_commit() {
    asm volatile("cp.async.commit_group;\n" ::: "memory");
}
template <int N> __device__ __forceinline__ void cp_wait() {
    asm volatile("cp.async.wait_group %0;\n" :: "n"(N) : "memory");
}

__device__ __forceinline__ void ldm_x4(uint32_t* r, uint32_t addr) {
    asm volatile("ldmatrix.sync.aligned.m8n8.x4.shared.b16 {%0,%1,%2,%3}, [%4];"
                 : "=r"(r[0]), "=r"(r[1]), "=r"(r[2]), "=r"(r[3]) : "r"(addr));
}

__device__ __forceinline__ void mma_f16(float* c, const uint32_t* a,
                                        uint32_t b0, uint32_t b1) {
    asm volatile("mma.sync.aligned.m16n8k16.row.col.f32.f16.f16.f32 "
                 "{%0,%1,%2,%3}, {%4,%5,%6,%7}, {%8,%9}, {%0,%1,%2,%3};"
                 : "+f"(c[0]), "+f"(c[1]), "+f"(c[2]), "+f"(c[3])
                 : "r"(a[0]), "r"(a[1]), "r"(a[2]), "r"(a[3]), "r"(b0), "r"(b1));
}

// ===========================================================================
// Single-term HMMA GEMM:  C = alpha * A@B^T   (fp16 NT, fp32 accum)
// CTA 128x128, BK=64, 256 threads, 8 warps x (32M x 64N) tiles,
// 2 x 32 KB cp.async stages, 2 CTAs/SM.
// Epilogue: fp32*alpha if Ch==null, else fp16 (alpha applied).
// ===========================================================================
#define ST_BYTES 32768u
#define SMEM_GEMM (2 * 32768 + 1024)

__global__ __launch_bounds__(256, 2)
void hgemm1(const __half* __restrict__ A,
            const __half* __restrict__ B,
            float* __restrict__ C,
            __half* __restrict__ Ch,
            int ldA, int ldB, int ldC, int kTiles,
            size_t sA, size_t sB, size_t sC, float alpha)
{
    extern __shared__ char smem_raw[];
    const uint32_t sbase = (smem_u32(smem_raw) + 1023u) & ~1023u;

    const int tid  = threadIdx.x;
    const int wid  = tid >> 5;
    const int lane = tid & 31;
    const int wm   = wid & 3;      // 4 M-warps -> 32 rows each
    const int wn   = wid >> 2;     // 2 N-warps -> 64 cols each

    const int row0 = blockIdx.y * 128;
    const int col0 = blockIdx.x * 128;

    A += (size_t)blockIdx.z * sA;
    B += (size_t)blockIdx.z * sB;

    float acc[2][8][4];
    #pragma unroll
    for (int mt = 0; mt < 2; mt++)
        #pragma unroll
        for (int j = 0; j < 8; j++)
            #pragma unroll
            for (int q = 0; q < 4; q++) acc[mt][j][q] = 0.f;

    auto load_stage = [&](int t) {
        const int kk = t * 64;
        const uint32_t st = sbase + (uint32_t)(t & 1) * ST_BYTES;
        #pragma unroll
        for (int q = 0; q < 4; q++) {
            int idx = tid + q * 256;
            int rr = idx >> 3, cc = idx & 7;
            uint32_t d = SWZ128((uint32_t)(rr * 128 + cc * 16));
            cp16(st +          d, A + (size_t)(row0 + rr) * ldA + kk + cc * 8);
            cp16(st + 16384u + d, B + (size_t)(col0 + rr) * ldB + kk + cc * 8);
        }
        cp_commit();
    };

    load_stage(0);

    const uint32_t lrow = (uint32_t)(lane & 15);
    const uint32_t lcol = (uint32_t)((lane >> 4) * 16);

    for (int t = 0; t < kTiles; t++) {
        if (t + 1 < kTiles) {
            load_stage(t + 1);
            cp_wait<1>();
        } else {
            cp_wait<0>();
        }
        __syncthreads();

        const uint32_t st = sbase + (uint32_t)(t & 1) * ST_BYTES;
        const uint32_t As = st;
        const uint32_t Bs = st + 16384u;

        #pragma unroll
        for (int k16 = 0; k16 < 4; k16++) {
            const uint32_t koff = (uint32_t)(k16 * 32) + lcol;
            uint32_t a[2][4];
            #pragma unroll
            for (int mt = 0; mt < 2; mt++)
                ldm_x4(a[mt], As + SWZ128((uint32_t)((wm * 32 + mt * 16 + lrow) * 128) + koff));
            uint32_t b[4][4];
            #pragma unroll
            for (int ng = 0; ng < 4; ng++)
                ldm_x4(b[ng], Bs + SWZ128((uint32_t)((wn * 64 + ng * 16 + lrow) * 128) + koff));
            #pragma unroll
            for (int mt = 0; mt < 2; mt++)
                #pragma unroll
                for (int j = 0; j < 8; j++) {
                    const int ng = j >> 1;
                    mma_f16(acc[mt][j], a[mt], b[ng][(j & 1) ? 1 : 0], b[ng][(j & 1) ? 3 : 2]);
                }
        }
        __syncthreads();
    }

    const int er = lane >> 2;
    const int ec = (lane & 3) * 2;
    if (Ch) {
        Ch += (size_t)blockIdx.z * sC;
        #pragma unroll
        for (int mt = 0; mt < 2; mt++) {
            const int rb = row0 + wm * 32 + mt * 16 + er;
            #pragma unroll
            for (int j = 0; j < 8; j++) {
                const int cb = col0 + wn * 64 + j * 8 + ec;
                __half2 H0, H1;
                H0.x = __float2half(alpha * acc[mt][j][0]);
                H0.y = __float2half(alpha * acc[mt][j][1]);
                H1.x = __float2half(alpha * acc[mt][j][2]);
                H1.y = __float2half(alpha * acc[mt][j][3]);
                *(__half2*)(Ch + (size_t)rb * ldC + cb)       = H0;
                *(__half2*)(Ch + (size_t)(rb + 8) * ldC + cb) = H1;
            }
        }
    } else {
        C += (size_t)blockIdx.z * sC;
        #pragma unroll
        for (int mt = 0; mt < 2; mt++) {
            const int rb = row0 + wm * 32 + mt * 16 + er;
            #pragma unroll
            for (int j = 0; j < 8; j++) {
                const int cb = col0 + wn * 64 + j * 8 + ec;
                *(float2*)(C + (size_t)rb * ldC + cb) =
                    make_float2(alpha * acc[mt][j][0], alpha * acc[mt][j][1]);
                *(float2*)(C + (size_t)(rb + 8) * ldC + cb) =
                    make_float2(alpha * acc[mt][j][2], alpha * acc[mt][j][3]);
            }
        }
    }
}

// ===========================================================================
// fp32 -> fp16 convert, 4 elems/thread
// ===========================================================================
__global__ __launch_bounds__(256)
void cvt_h(const float* __restrict__ src, __half* __restrict__ dst, size_t n4)
{
    size_t i = (size_t)blockIdx.x * 256 + threadIdx.x;
    if (i >= n4) return;
    float4 v = ((const float4*)src)[i];
    __half2 H0, H1;
    H0.x = __float2half(v.x); H0.y = __float2half(v.y);
    H1.x = __float2half(v.z); H1.y = __float2half(v.w);
    ((__half2*)dst)[2 * i + 0] = H0;
    ((__half2*)dst)[2 * i + 1] = H1;
}

// ===========================================================================
// fp16 [b,s,d] -> fp16 [b,d,s] transpose (64x64 tiles), grid.z = batch
// ===========================================================================
__global__ __launch_bounds__(256)
void transpose_h(const __half* __restrict__ src, __half* __restrict__ dst)
{
    __shared__ __half t[64][65];
    const int b  = blockIdx.z;
    const int s0 = blockIdx.x * 64, d0 = blockIdx.y * 64;
    const int tid = threadIdx.x;
    src += (size_t)b * SEQ * DIM;
    dst += (size_t)b * DIM * SEQ;

    #pragma unroll
    for (int q = 0; q < 8; q++) {
        int i = tid + q * 256;
        int row = i >> 5, cp = i & 31;
        __half2 v = *(const __half2*)(src + (size_t)(s0 + row) * DIM + d0 + cp * 2);
        t[row][cp * 2 + 0] = v.x;
        t[row][cp * 2 + 1] = v.y;
    }
    __syncthreads();
    #pragma unroll
    for (int q = 0; q < 8; q++) {
        int i = tid + q * 256;
        int drow = i >> 5, sp = i & 31;
        __half2 o;
        o.x = t[sp * 2 + 0][drow];
        o.y = t[sp * 2 + 1][drow];
        *(__half2*)(dst + (size_t)(d0 + drow) * SEQ + s0 + sp * 2) = o;
    }
}

// ===========================================================================
// Row softmax (registers), fp16 output
// ===========================================================================
__global__ __launch_bounds__(256)
void softmax_h(const float* __restrict__ S, __half* __restrict__ hi)
{
    __shared__ float red_m[8];
    __shared__ float red_s[8];
    const size_t base = (size_t)blockIdx.x * SEQ;
    const int tid  = threadIdx.x;
    const int wid  = tid >> 5;
    const int lane = tid & 31;

    const float4* row4 = (const float4*)(S + base);
    float4 v0 = row4[tid];
    float4 v1 = row4[tid + 256];

    float m = fmaxf(fmaxf(fmaxf(v0.x, v0.y), fmaxf(v0.z, v0.w)),
                    fmaxf(fmaxf(v1.x, v1.y), fmaxf(v1.z, v1.w)));
    #pragma unroll
    for (int o = 16; o > 0; o >>= 1) m = fmaxf(m, __shfl_xor_sync(~0u, m, o));
    if (lane == 0) red_m[wid] = m;
    __syncthreads();
    m = red_m[0];
    #pragma unroll
    for (int i = 1; i < 8; i++) m = fmaxf(m, red_m[i]);

    v0.x = __expf(v0.x - m); v0.y = __expf(v0.y - m);
    v0.z = __expf(v0.z - m); v0.w = __expf(v0.w - m);
    v1.x = __expf(v1.x - m); v1.y = __expf(v1.y - m);
    v1.z = __expf(v1.z - m); v1.w = __expf(v1.w - m);

    float s = v0.x + v0.y + v0.z + v0.w + v1.x + v1.y + v1.z + v1.w;
    #pragma unroll
    for (int o = 16; o > 0; o >>= 1) s += __shfl_xor_sync(~0u, s, o);
    if (lane == 0) red_s[wid] = s;
    __syncthreads();
    s = red_s[0];
    #pragma unroll
    for (int i = 1; i < 8; i++) s += red_s[i];
    const float inv = 1.f / s;

    auto emit = [&](float4 v, int c0) {
        __half2 H0, H1;
        H0.x = __float2half(v.x * inv); H0.y = __float2half(v.y * inv);
        H1.x = __float2half(v.z * inv); H1.y = __float2half(v.w * inv);
        *(__half2*)(hi + base + c0)     = H0;
        *(__half2*)(hi + base + c0 + 2) = H1;
    };
    emit(v0, tid * 4);
    emit(v1, (tid + 256) * 4);
}

// ===========================================================================
extern "C" void kernel_launch(void* const* d_in, const int* in_sizes, int n_in,
                              void* d_out, int out_size)
{
    const float* x  = (const float*)d_in[0];
    const float* Wq = (const float*)d_in[1];
    const float* Wk = (const float*)d_in[2];
    const float* Wv = (const float*)d_in[3];
    float* out = (float*)d_out;

    cudaFuncSetAttribute(hgemm1, cudaFuncAttributeMaxDynamicSharedMemorySize, SMEM_GEMM);

    unsigned char* base;
    cudaGetSymbolAddress((void**)&base, g_scratch);

    __half* xh   = (__half*)(base + O_XH);
    __half* wh   = (__half*)(base + O_WH);
    __half* qkvh = (__half*)(base + O_QKVH);
    __half* vt   = (__half*)(base + O_VT);
    float*  Sf   = (float*)(base + O_S);
    __half* sh   = (__half*)(base + O_SH);

    const float scale = 0.044194173824159216f;   // 1/sqrt(512)

    // 1. convert x, W to fp16
    cvt_h<<<(unsigned)(SZ_X / 4 / 256), 256>>>(x, xh, SZ_X / 4);
    cvt_h<<<DIM * DIM / 4 / 256, 256>>>(Wq, wh,                 DIM * DIM / 4);
    cvt_h<<<DIM * DIM / 4 / 256, 256>>>(Wk, wh + DIM * DIM,     DIM * DIM / 4);
    cvt_h<<<DIM * DIM / 4 / 256, 256>>>(Wv, wh + 2 * DIM * DIM, DIM * DIM / 4);

    // 2. QKV projections, fp16 epilogue (grid.z batches the 3 weights)
    {
        dim3 g(DIM / 128, MTOT / 128, 3);
        hgemm1<<<g, 256, SMEM_GEMM>>>(xh, wh, nullptr, qkvh,
                                      DIM, DIM, DIM, DIM / 64,
                                      0, (size_t)DIM * DIM, SZ_X, 1.0f);
    }

    // 3. transpose V -> V^T
    {
        dim3 g(SEQ / 64, DIM / 64, BATCH);
        transpose_h<<<g, 256>>>(qkvh + 2 * SZ_X, vt);
    }

    // 4. scores = Q @ K^T * scale  (fp32 epilogue)
    {
        dim3 g(SEQ / 128, SEQ / 128, BATCH);
        hgemm1<<<g, 256, SMEM_GEMM>>>(qkvh, qkvh + SZ_X, Sf, nullptr,
                                      DIM, DIM, SEQ, DIM / 64,
                                      (size_t)SEQ * DIM, (size_t)SEQ * DIM,
                                      (size_t)SEQ * SEQ, scale);
    }

    // 5. softmax -> fp16 attn
    softmax_h<<<BATCH * SEQ, 256>>>(Sf, sh);

    // 6. out = attn @ V  (fp32 epilogue)
    {
        dim3 g(DIM / 128, SEQ / 128, BATCH);
        hgemm1<<<g, 256, SMEM_GEMM>>>(sh, vt, out, nullptr,
                                      SEQ, SEQ, DIM, SEQ / 64,
                                      (size_t)SEQ * SEQ, (size_t)DIM * SEQ,
                                      (size_t)SEQ * DIM, 1.0f);
    }
}

// round 10
// speedup vs baseline: 4.2342x; 1.0234x over previous
#include <cuda_runtime.h>
#include <cuda_fp16.h>
#include <math.h>
#include <stdint.h>

#define BATCH 8
#define SEQ   2048
#define DIM   512
#define MTOT  (BATCH*SEQ)        // 16384

// ===========================================================================
// Scratch memory (single __device__ array; no allocation anywhere)
// ===========================================================================
#define SZ_X ((size_t)MTOT * DIM)                     // 8,388,608 elems
static const size_t O_XH   = 0;                                 // fp16 SZ_X
static const size_t O_WH   = O_XH  + SZ_X * 2;                  // fp16 3*DIM*DIM
static const size_t O_QKVH = O_WH  + (size_t)3 * DIM * DIM * 2; // fp16 3*SZ_X
static const size_t O_VT   = O_QKVH + (size_t)3 * SZ_X * 2;     // fp16 SZ_X (V^T)
static const size_t O_SH   = O_VT  + SZ_X * 2;                  // fp16 B*S*S
static const size_t SCRATCH_TOTAL = O_SH + (size_t)BATCH * SEQ * SEQ * 2;

__device__ __align__(1024) unsigned char g_scratch[SCRATCH_TOTAL];

// ===========================================================================
// PTX helpers (arch-agnostic: cp.async / ldmatrix / mma.sync only)
// ===========================================================================
__device__ __forceinline__ uint32_t smem_u32(const void* p) {
    uint32_t a;
    asm("{ .reg .u64 t; cvta.to.shared.u64 t, %1; cvt.u32.u64 %0, t; }"
        : "=r"(a) : "l"(p));
    return a;
}

#define SWZ128(x) ((x) ^ (((x) >> 3) & 0x70))

__device__ __forceinline__ void cp16(uint32_t dst, const void* src) {
    asm volatile("cp.async.cg.shared.global [%0], [%1], 16;\n"
                 :: "r"(dst), "l"(src));
}
__device__ __forceinline__ void cp_commit() {
    asm volatile("cp.async.commit_group;\n" ::: "memory");
}
template <int N> __device__ __forceinline__ void cp_wait() {
    asm volatile("cp.async.wait_group %0;\n" :: "n"(N) : "memory");
}

__device__ __forceinline__ void ldm_x4(uint32_t* r, uint32_t addr) {
    asm volatile("ldmatrix.sync.aligned.m8n8.x4.shared.b16 {%0,%1,%2,%3}, [%4];"
                 : "=r"(r[0]), "=r"(r[1]), "=r"(r[2]), "=r"(r[3]) : "r"(addr));
}

__device__ __forceinline__ void mma_f16(float* c, const uint32_t* a,
                                        uint32_t b0, uint32_t b1) {
    asm volatile("mma.sync.aligned.m16n8k16.row.col.f32.f16.f16.f32 "
                 "{%0,%1,%2,%3}, {%4,%5,%6,%7}, {%8,%9}, {%0,%1,%2,%3};"
                 : "+f"(c[0]), "+f"(c[1]), "+f"(c[2]), "+f"(c[3])
                 : "r"(a[0]), "r"(a[1]), "r"(a[2]), "r"(a[3]), "r"(b0), "r"(b1));
}

// ===========================================================================
// Single-term HMMA GEMM:  C = alpha * A@B^T   (fp16 NT, fp32 accum)
// CTA 128x128, BK=64, 256 threads, 8 warps x (32M x 64N) tiles,
// 3-stage cp.async pipeline (3 x 32 KB), ONE barrier per k-iter, 2 CTAs/SM.
// Epilogue: fp32*alpha if Ch==null, else fp16 (alpha applied).
// ===========================================================================
#define ST_BYTES 32768u
#define SMEM_GEMM (3 * 32768 + 1024)

__global__ __launch_bounds__(256, 2)
void hgemm1(const __half* __restrict__ A,
            const __half* __restrict__ B,
            float* __restrict__ C,
            __half* __restrict__ Ch,
            int ldA, int ldB, int ldC, int kTiles,
            size_t sA, size_t sB, size_t sC, float alpha)
{
    extern __shared__ char smem_raw[];
    const uint32_t sbase = (smem_u32(smem_raw) + 1023u) & ~1023u;

    const int tid  = threadIdx.x;
    const int wid  = tid >> 5;
    const int lane = tid & 31;
    const int wm   = wid & 3;      // 4 M-warps -> 32 rows each
    const int wn   = wid >> 2;     // 2 N-warps -> 64 cols each

    const int row0 = blockIdx.y * 128;
    const int col0 = blockIdx.x * 128;

    A += (size_t)blockIdx.z * sA;
    B += (size_t)blockIdx.z * sB;

    float acc[2][8][4];
    #pragma unroll
    for (int mt = 0; mt < 2; mt++)
        #pragma unroll
        for (int j = 0; j < 8; j++)
            #pragma unroll
            for (int q = 0; q < 4; q++) acc[mt][j][q] = 0.f;

    auto load_stage = [&](int t) {
        const int kk = t * 64;
        const uint32_t st = sbase + (uint32_t)(t % 3) * ST_BYTES;
        #pragma unroll
        for (int q = 0; q < 4; q++) {
            int idx = tid + q * 256;
            int rr = idx >> 3, cc = idx & 7;
            uint32_t d = SWZ128((uint32_t)(rr * 128 + cc * 16));
            cp16(st +          d, A + (size_t)(row0 + rr) * ldA + kk + cc * 8);
            cp16(st + 16384u + d, B + (size_t)(col0 + rr) * ldB + kk + cc * 8);
        }
        cp_commit();
    };

    load_stage(0);
    if (kTiles > 1) load_stage(1);

    const uint32_t lrow = (uint32_t)(lane & 15);
    const uint32_t lcol = (uint32_t)((lane >> 4) * 16);

    for (int t = 0; t < kTiles; t++) {
        if (t + 1 < kTiles) cp_wait<1>(); else cp_wait<0>();
        __syncthreads();
        // stage t resident; buffer (t+2)%3 free (compute t-1 done by barrier)
        if (t + 2 < kTiles) load_stage(t + 2);

        const uint32_t st = sbase + (uint32_t)(t % 3) * ST_BYTES;
        const uint32_t As = st;
        const uint32_t Bs = st + 16384u;

        #pragma unroll
        for (int k16 = 0; k16 < 4; k16++) {
            const uint32_t koff = (uint32_t)(k16 * 32) + lcol;
            uint32_t a[2][4];
            #pragma unroll
            for (int mt = 0; mt < 2; mt++)
                ldm_x4(a[mt], As + SWZ128((uint32_t)((wm * 32 + mt * 16 + lrow) * 128) + koff));
            uint32_t b[4][4];
            #pragma unroll
            for (int ng = 0; ng < 4; ng++)
                ldm_x4(b[ng], Bs + SWZ128((uint32_t)((wn * 64 + ng * 16 + lrow) * 128) + koff));
            #pragma unroll
            for (int mt = 0; mt < 2; mt++)
                #pragma unroll
                for (int j = 0; j < 8; j++) {
                    const int ng = j >> 1;
                    mma_f16(acc[mt][j], a[mt], b[ng][(j & 1) ? 1 : 0], b[ng][(j & 1) ? 3 : 2]);
                }
        }
    }

    const int er = lane >> 2;
    const int ec = (lane & 3) * 2;
    if (Ch) {
        Ch += (size_t)blockIdx.z * sC;
        #pragma unroll
        for (int mt = 0; mt < 2; mt++) {
            const int rb = row0 + wm * 32 + mt * 16 + er;
            #pragma unroll
            for (int j = 0; j < 8; j++) {
                const int cb = col0 + wn * 64 + j * 8 + ec;
                __half2 H0, H1;
                H0.x = __float2half(alpha * acc[mt][j][0]);
                H0.y = __float2half(alpha * acc[mt][j][1]);
                H1.x = __float2half(alpha * acc[mt][j][2]);
                H1.y = __float2half(alpha * acc[mt][j][3]);
                *(__half2*)(Ch + (size_t)rb * ldC + cb)       = H0;
                *(__half2*)(Ch + (size_t)(rb + 8) * ldC + cb) = H1;
            }
        }
    } else {
        C += (size_t)blockIdx.z * sC;
        #pragma unroll
        for (int mt = 0; mt < 2; mt++) {
            const int rb = row0 + wm * 32 + mt * 16 + er;
            #pragma unroll
            for (int j = 0; j < 8; j++) {
                const int cb = col0 + wn * 64 + j * 8 + ec;
                *(float2*)(C + (size_t)rb * ldC + cb) =
                    make_float2(alpha * acc[mt][j][0], alpha * acc[mt][j][1]);
                *(float2*)(C + (size_t)(rb + 8) * ldC + cb) =
                    make_float2(alpha * acc[mt][j][2], alpha * acc[mt][j][3]);
            }
        }
    }
}

// ===========================================================================
// fp32 -> fp16 convert, 4 elems/thread
// ===========================================================================
__global__ __launch_bounds__(256)
void cvt_h(const float* __restrict__ src, __half* __restrict__ dst, size_t n4)
{
    size_t i = (size_t)blockIdx.x * 256 + threadIdx.x;
    if (i >= n4) return;
    float4 v = ((const float4*)src)[i];
    __half2 H0, H1;
    H0.x = __float2half(v.x); H0.y = __float2half(v.y);
    H1.x = __float2half(v.z); H1.y = __float2half(v.w);
    ((__half2*)dst)[2 * i + 0] = H0;
    ((__half2*)dst)[2 * i + 1] = H1;
}

// ===========================================================================
// fp16 [b,s,d] -> fp16 [b,d,s] transpose (64x64 tiles), grid.z = batch
// ===========================================================================
__global__ __launch_bounds__(256)
void transpose_h(const __half* __restrict__ src, __half* __restrict__ dst)
{
    __shared__ __half t[64][65];
    const int b  = blockIdx.z;
    const int s0 = blockIdx.x * 64, d0 = blockIdx.y * 64;
    const int tid = threadIdx.x;
    src += (size_t)b * SEQ * DIM;
    dst += (size_t)b * DIM * SEQ;

    #pragma unroll
    for (int q = 0; q < 8; q++) {
        int i = tid + q * 256;
        int row = i >> 5, cp = i & 31;
        __half2 v = *(const __half2*)(src + (size_t)(s0 + row) * DIM + d0 + cp * 2);
        t[row][cp * 2 + 0] = v.x;
        t[row][cp * 2 + 1] = v.y;
    }
    __syncthreads();
    #pragma unroll
    for (int q = 0; q < 8; q++) {
        int i = tid + q * 256;
        int drow = i >> 5, sp = i & 31;
        __half2 o;
        o.x = t[sp * 2 + 0][drow];
        o.y = t[sp * 2 + 1][drow];
        *(__half2*)(dst + (size_t)(d0 + drow) * SEQ + s0 + sp * 2) = o;
    }
}

// ===========================================================================
// Row softmax, in place on fp16 scores (fp32 math in registers)
// ===========================================================================
__global__ __launch_bounds__(256)
void softmax_h16(__half* __restrict__ S)
{
    __shared__ float red_m[8];
    __shared__ float red_s[8];
    const size_t base = (size_t)blockIdx.x * SEQ;
    const int tid  = threadIdx.x;
    const int wid  = tid >> 5;
    const int lane = tid & 31;

    // 8 halves per thread (one 16B load)
    uint4 raw = ((const uint4*)(S + base))[tid];
    __half2 h[4];
    h[0] = *(__half2*)&raw.x; h[1] = *(__half2*)&raw.y;
    h[2] = *(__half2*)&raw.z; h[3] = *(__half2*)&raw.w;
    float v[8];
    #pragma unroll
    for (int i = 0; i < 4; i++) {
        v[2 * i + 0] = __half2float(h[i].x);
        v[2 * i + 1] = __half2float(h[i].y);
    }

    float m = v[0];
    #pragma unroll
    for (int i = 1; i < 8; i++) m = fmaxf(m, v[i]);
    #pragma unroll
    for (int o = 16; o > 0; o >>= 1) m = fmaxf(m, __shfl_xor_sync(~0u, m, o));
    if (lane == 0) red_m[wid] = m;
    __syncthreads();
    m = red_m[0];
    #pragma unroll
    for (int i = 1; i < 8; i++) m = fmaxf(m, red_m[i]);

    float s = 0.f;
    #pragma unroll
    for (int i = 0; i < 8; i++) { v[i] = __expf(v[i] - m); s += v[i]; }
    #pragma unroll
    for (int o = 16; o > 0; o >>= 1) s += __shfl_xor_sync(~0u, s, o);
    if (lane == 0) red_s[wid] = s;
    __syncthreads();
    s = red_s[0];
    #pragma unroll
    for (int i = 1; i < 8; i++) s += red_s[i];
    const float inv = 1.f / s;

    #pragma unroll
    for (int i = 0; i < 4; i++) {
        h[i].x = __float2half(v[2 * i + 0] * inv);
        h[i].y = __float2half(v[2 * i + 1] * inv);
    }
    uint4 outw;
    outw.x = *(uint32_t*)&h[0]; outw.y = *(uint32_t*)&h[1];
    outw.z = *(uint32_t*)&h[2]; outw.w = *(uint32_t*)&h[3];
    ((uint4*)(S + base))[tid] = outw;
}

// ===========================================================================
extern "C" void kernel_launch(void* const* d_in, const int* in_sizes, int n_in,
                              void* d_out, int out_size)
{
    const float* x  = (const float*)d_in[0];
    const float* Wq = (const float*)d_in[1];
    const float* Wk = (const float*)d_in[2];
    const float* Wv = (const float*)d_in[3];
    float* out = (float*)d_out;

    cudaFuncSetAttribute(hgemm1, cudaFuncAttributeMaxDynamicSharedMemorySize, SMEM_GEMM);

    unsigned char* base;
    cudaGetSymbolAddress((void**)&base, g_scratch);

    __half* xh   = (__half*)(base + O_XH);
    __half* wh   = (__half*)(base + O_WH);
    __half* qkvh = (__half*)(base + O_QKVH);
    __half* vt   = (__half*)(base + O_VT);
    __half* sh   = (__half*)(base + O_SH);

    const float scale = 0.044194173824159216f;   // 1/sqrt(512)

    // 1. convert x, W to fp16
    cvt_h<<<(unsigned)(SZ_X / 4 / 256), 256>>>(x, xh, SZ_X / 4);
    cvt_h<<<DIM * DIM / 4 / 256, 256>>>(Wq, wh,                 DIM * DIM / 4);
    cvt_h<<<DIM * DIM / 4 / 256, 256>>>(Wk, wh + DIM * DIM,     DIM * DIM / 4);
    cvt_h<<<DIM * DIM / 4 / 256, 256>>>(Wv, wh + 2 * DIM * DIM, DIM * DIM / 4);

    // 2. QKV projections, fp16 epilogue (grid.z batches the 3 weights)
    {
        dim3 g(DIM / 128, MTOT / 128, 3);
        hgemm1<<<g, 256, SMEM_GEMM>>>(xh, wh, nullptr, qkvh,
                                      DIM, DIM, DIM, DIM / 64,
                                      0, (size_t)DIM * DIM, SZ_X, 1.0f);
    }

    // 3. transpose V -> V^T
    {
        dim3 g(SEQ / 64, DIM / 64, BATCH);
        transpose_h<<<g, 256>>>(qkvh + 2 * SZ_X, vt);
    }

    // 4. scores = Q @ K^T * scale, written directly as fp16
    {
        dim3 g(SEQ / 128, SEQ / 128, BATCH);
        hgemm1<<<g, 256, SMEM_GEMM>>>(qkvh, qkvh + SZ_X, nullptr, sh,
                                      DIM, DIM, SEQ, DIM / 64,
                                      (size_t)SEQ * DIM, (size_t)SEQ * DIM,
                                      (size_t)SEQ * SEQ, scale);
    }

    // 5. softmax in place on fp16 scores
    softmax_h16<<<BATCH * SEQ, 256>>>(sh);

    // 6. out = attn @ V  (fp32 epilogue)
    {
        dim3 g(DIM / 128, SEQ / 128, BATCH);
        hgemm1<<<g, 256, SMEM_GEMM>>>(sh, vt, out, nullptr,
                                      SEQ, SEQ, DIM, SEQ / 64,
                                      (size_t)SEQ * SEQ, (size_t)DIM * SEQ,
                                      (size_t)SEQ * DIM, 1.0f);
    }
}